// round 1
// baseline (speedup 1.0000x reference)
#include <cuda_runtime.h>

#define N_NODES 50000
#define N_EDGES 800000
#define DIM 256
#define N_GRAPHS 500
#define N_OUT 10
#define BN_EPS 1e-5f

// ---------------- scratch (static device globals; no allocation) ----------------
__device__ float g_agg[(size_t)N_NODES * DIM];
__device__ float g_tmp[(size_t)N_NODES * DIM];
__device__ float g_h1[(size_t)N_NODES * DIM];
__device__ float g_h2[(size_t)N_NODES * DIM];
__device__ float g_pool[(size_t)N_GRAPHS * 2 * DIM];
__device__ int   g_idx_is64;

// ---------------- dtype detection (int64 vs int32 indices) ----------------
__global__ void detect_kernel(const long long* __restrict__ ei) {
    if (threadIdx.x == 0 && blockIdx.x == 0) {
        int ok = 1;
        for (int i = 0; i < 64; i++) {
            long long v = ei[i];
            if (v < 0 || v >= N_NODES) ok = 0;
        }
        g_idx_is64 = ok;
    }
}

__device__ __forceinline__ int load_idx(const void* p, int i) {
    if (g_idx_is64) return (int)((const long long*)p)[i];
    return ((const int*)p)[i];
}

// ---------------- copy (agg = src) ----------------
__global__ void copy_kernel(const float* __restrict__ src, float* __restrict__ dst) {
    int i = blockIdx.x * blockDim.x + threadIdx.x;   // float4 index
    ((float4*)dst)[i] = ((const float4*)src)[i];
}

// ---------------- edge scatter: agg[dst] += x[src] ----------------
__global__ void scatter_kernel(const float* __restrict__ x, const void* __restrict__ ei,
                               float* __restrict__ agg) {
    int e = blockIdx.x * 8 + (threadIdx.x >> 5);
    if (e >= N_EDGES) return;
    int lane = threadIdx.x & 31;
    int s = load_idx(ei, e);
    int d = load_idx(ei, N_EDGES + e);
    const float4* xs = (const float4*)(x + (size_t)s * DIM);
    float* ad = agg + (size_t)d * DIM;
#pragma unroll
    for (int h = 0; h < 2; h++) {
        int idx = lane + h * 32;            // float4 index 0..63
        float4 v = xs[idx];
        float* p = ad + idx * 4;
        atomicAdd(p + 0, v.x);
        atomicAdd(p + 1, v.y);
        atomicAdd(p + 2, v.z);
        atomicAdd(p + 3, v.w);
    }
}

// ---------------- fused GEMM (M x 256 @ 256 x 256) + bias [+BN] + ReLU ----------------
// BM=128, BN=128, BK=16, TM=TN=8, 256 threads.
template <bool DO_BN>
__global__ __launch_bounds__(256) void gemm_epi_kernel(
    const float* __restrict__ A, const float* __restrict__ W,
    const float* __restrict__ bias,
    const float* __restrict__ gamma, const float* __restrict__ beta,
    const float* __restrict__ mean,  const float* __restrict__ var,
    float* __restrict__ C, int M)
{
    __shared__ float As[16][128];
    __shared__ float Bs[16][128];
    const int tid = threadIdx.x;
    const int ty = tid >> 4;          // 0..15
    const int tx = tid & 15;          // 0..15
    const int rowBase = blockIdx.x * 128;
    const int colBase = blockIdx.y * 128;

    const int aRow  = tid >> 2;       // 0..63
    const int aCol  = (tid & 3) * 4;  // 0,4,8,12
    const int bRow  = tid >> 5;       // 0..7
    const int bCol  = (tid & 31) * 4; // 0..124

    float acc[8][8];
#pragma unroll
    for (int i = 0; i < 8; i++)
#pragma unroll
        for (int j = 0; j < 8; j++) acc[i][j] = 0.f;

    for (int kt = 0; kt < 256; kt += 16) {
#pragma unroll
        for (int h = 0; h < 2; h++) {
            int r = rowBase + aRow + h * 64;
            int rc = r < M ? r : (M - 1);
            float4 v = *(const float4*)(A + (size_t)rc * 256 + kt + aCol);
            As[aCol + 0][aRow + h * 64] = v.x;
            As[aCol + 1][aRow + h * 64] = v.y;
            As[aCol + 2][aRow + h * 64] = v.z;
            As[aCol + 3][aRow + h * 64] = v.w;
        }
#pragma unroll
        for (int h = 0; h < 2; h++) {
            int r = kt + bRow + h * 8;
            *(float4*)&Bs[bRow + h * 8][bCol] = *(const float4*)(W + (size_t)r * 256 + colBase + bCol);
        }
        __syncthreads();
#pragma unroll
        for (int k = 0; k < 16; k++) {
            float a[8], b[8];
            *(float4*)(a)     = *(const float4*)&As[k][ty * 8];
            *(float4*)(a + 4) = *(const float4*)&As[k][ty * 8 + 4];
            *(float4*)(b)     = *(const float4*)&Bs[k][tx * 8];
            *(float4*)(b + 4) = *(const float4*)&Bs[k][tx * 8 + 4];
#pragma unroll
            for (int i = 0; i < 8; i++)
#pragma unroll
                for (int j = 0; j < 8; j++)
                    acc[i][j] = fmaf(a[i], b[j], acc[i][j]);
        }
        __syncthreads();
    }

    // epilogue: out = relu(acc*sc + sh)
    float sc[8], sh[8];
#pragma unroll
    for (int j = 0; j < 8; j++) {
        int c = colBase + tx * 8 + j;
        float bv = bias[c];
        if (DO_BN) {
            float s = gamma[c] * rsqrtf(var[c] + BN_EPS);
            sc[j] = s;
            sh[j] = beta[c] - mean[c] * s + bv * s;
        } else {
            sc[j] = 1.f;
            sh[j] = bv;
        }
    }
#pragma unroll
    for (int i = 0; i < 8; i++) {
        int r = rowBase + ty * 8 + i;
        if (r < M) {
            float4 o0, o1;
            o0.x = fmaxf(acc[i][0] * sc[0] + sh[0], 0.f);
            o0.y = fmaxf(acc[i][1] * sc[1] + sh[1], 0.f);
            o0.z = fmaxf(acc[i][2] * sc[2] + sh[2], 0.f);
            o0.w = fmaxf(acc[i][3] * sc[3] + sh[3], 0.f);
            o1.x = fmaxf(acc[i][4] * sc[4] + sh[4], 0.f);
            o1.y = fmaxf(acc[i][5] * sc[5] + sh[5], 0.f);
            o1.z = fmaxf(acc[i][6] * sc[6] + sh[6], 0.f);
            o1.w = fmaxf(acc[i][7] * sc[7] + sh[7], 0.f);
            float* crow = C + (size_t)r * 256 + colBase + tx * 8;
            *(float4*)(crow)     = o0;
            *(float4*)(crow + 4) = o1;
        }
    }
}

// ---------------- pooling: pool[g][0:256]+=h1 row, pool[g][256:512]+=h2 row ----------------
__global__ void zero_pool_kernel() {
    int i = blockIdx.x * blockDim.x + threadIdx.x;
    if (i < N_GRAPHS * 2 * DIM) g_pool[i] = 0.f;
}

__global__ void pool_kernel(const float* __restrict__ h1, const float* __restrict__ h2,
                            const void* __restrict__ batch) {
    int wid = blockIdx.x * 8 + (threadIdx.x >> 5);
    int base = wid * 16;
    if (base >= N_NODES) return;
    int lane = threadIdx.x & 31;
    int end = base + 16; if (end > N_NODES) end = N_NODES;

    float4 a0 = {0,0,0,0}, a1 = {0,0,0,0}, b0 = {0,0,0,0}, b1 = {0,0,0,0};
    int cur = load_idx(batch, base);
    for (int n = base; n < end; n++) {
        int g = load_idx(batch, n);
        if (g != cur) {
            float* p = g_pool + (size_t)cur * 512 + lane * 4;
            atomicAdd(p + 0, a0.x); atomicAdd(p + 1, a0.y); atomicAdd(p + 2, a0.z); atomicAdd(p + 3, a0.w);
            atomicAdd(p + 128, a1.x); atomicAdd(p + 129, a1.y); atomicAdd(p + 130, a1.z); atomicAdd(p + 131, a1.w);
            atomicAdd(p + 256, b0.x); atomicAdd(p + 257, b0.y); atomicAdd(p + 258, b0.z); atomicAdd(p + 259, b0.w);
            atomicAdd(p + 384, b1.x); atomicAdd(p + 385, b1.y); atomicAdd(p + 386, b1.z); atomicAdd(p + 387, b1.w);
            a0 = a1 = b0 = b1 = make_float4(0,0,0,0);
            cur = g;
        }
        const float4* r1 = (const float4*)(h1 + (size_t)n * 256);
        const float4* r2 = (const float4*)(h2 + (size_t)n * 256);
        float4 v;
        v = r1[lane];      a0.x += v.x; a0.y += v.y; a0.z += v.z; a0.w += v.w;
        v = r1[lane + 32]; a1.x += v.x; a1.y += v.y; a1.z += v.z; a1.w += v.w;
        v = r2[lane];      b0.x += v.x; b0.y += v.y; b0.z += v.z; b0.w += v.w;
        v = r2[lane + 32]; b1.x += v.x; b1.y += v.y; b1.z += v.z; b1.w += v.w;
    }
    float* p = g_pool + (size_t)cur * 512 + lane * 4;
    atomicAdd(p + 0, a0.x); atomicAdd(p + 1, a0.y); atomicAdd(p + 2, a0.z); atomicAdd(p + 3, a0.w);
    atomicAdd(p + 128, a1.x); atomicAdd(p + 129, a1.y); atomicAdd(p + 130, a1.z); atomicAdd(p + 131, a1.w);
    atomicAdd(p + 256, b0.x); atomicAdd(p + 257, b0.y); atomicAdd(p + 258, b0.z); atomicAdd(p + 259, b0.w);
    atomicAdd(p + 384, b1.x); atomicAdd(p + 385, b1.y); atomicAdd(p + 386, b1.z); atomicAdd(p + 387, b1.w);
}

// ---------------- head: [500,512] @ [512,768] +b relu -> @ [768,10] +b -> log_softmax ----------------
__global__ __launch_bounds__(256) void head_kernel(
    const float* __restrict__ W1, const float* __restrict__ b1,
    const float* __restrict__ W2, const float* __restrict__ b2,
    float* __restrict__ out)
{
    __shared__ float Ps[8][512];
    __shared__ float Hs[8][768];
    __shared__ float Os[8][10];
    int tid = threadIdx.x;
    int rowBase = blockIdx.x * 8;
    int nrows = N_GRAPHS - rowBase; if (nrows > 8) nrows = 8;

    for (int i = tid; i < 8 * 512; i += 256) {
        int r = i >> 9, c = i & 511;
        Ps[r][c] = (r < nrows) ? g_pool[(size_t)(rowBase + r) * 512 + c] : 0.f;
    }
    __syncthreads();

    for (int n = tid; n < 768; n += 256) {
        float acc[8];
#pragma unroll
        for (int r = 0; r < 8; r++) acc[r] = 0.f;
        for (int k = 0; k < 512; k++) {
            float w = W1[(size_t)k * 768 + n];
#pragma unroll
            for (int r = 0; r < 8; r++) acc[r] = fmaf(Ps[r][k], w, acc[r]);
        }
        float bb = b1[n];
#pragma unroll
        for (int r = 0; r < 8; r++) Hs[r][n] = fmaxf(acc[r] + bb, 0.f);
    }
    __syncthreads();

    if (tid < 80) {
        int r = tid / 10, c = tid % 10;
        float acc = b2[c];
        for (int k = 0; k < 768; k++) acc = fmaf(Hs[r][k], W2[(size_t)k * 10 + c], acc);
        Os[r][c] = acc;
    }
    __syncthreads();

    if (tid < nrows) {
        int r = tid;
        float mx = -1e30f;
        for (int c = 0; c < 10; c++) mx = fmaxf(mx, Os[r][c]);
        float s = 0.f;
        for (int c = 0; c < 10; c++) s += expf(Os[r][c] - mx);
        float lse = mx + logf(s);
        for (int c = 0; c < 10; c++) out[(size_t)(rowBase + r) * 10 + c] = Os[r][c] - lse;
    }
}

// ---------------- launch ----------------
extern "C" void kernel_launch(void* const* d_in, const int* in_sizes, int n_in,
                              void* d_out, int out_size) {
    const float* x     = (const float*)d_in[0];
    const void*  ei    = d_in[1];
    const void*  batch = d_in[2];
    const float* W1a = (const float*)d_in[3];
    const float* b1a = (const float*)d_in[4];
    const float* g1a = (const float*)d_in[5];
    const float* be1a= (const float*)d_in[6];
    const float* m1a = (const float*)d_in[7];
    const float* v1a = (const float*)d_in[8];
    const float* W2a = (const float*)d_in[9];
    const float* b2a = (const float*)d_in[10];
    const float* W1b = (const float*)d_in[11];
    const float* b1b = (const float*)d_in[12];
    const float* g1b = (const float*)d_in[13];
    const float* be1b= (const float*)d_in[14];
    const float* m1b = (const float*)d_in[15];
    const float* v1b = (const float*)d_in[16];
    const float* W2b = (const float*)d_in[17];
    const float* b2b = (const float*)d_in[18];
    const float* lin1W = (const float*)d_in[19];
    const float* lin1b = (const float*)d_in[20];
    const float* lin2W = (const float*)d_in[21];
    const float* lin2b = (const float*)d_in[22];
    float* out = (float*)d_out;

    float *agg, *tmp, *h1, *h2;
    cudaGetSymbolAddress((void**)&agg, g_agg);
    cudaGetSymbolAddress((void**)&tmp, g_tmp);
    cudaGetSymbolAddress((void**)&h1,  g_h1);
    cudaGetSymbolAddress((void**)&h2,  g_h2);

    const int copyGrid = (N_NODES * DIM / 4) / 256;       // 12500
    const int scatGrid = (N_EDGES + 7) / 8;               // 100000
    dim3 gemmGrid((N_NODES + 127) / 128, 2);

    detect_kernel<<<1, 32>>>((const long long*)ei);

    // layer 1
    copy_kernel<<<copyGrid, 256>>>(x, agg);
    scatter_kernel<<<scatGrid, 256>>>(x, ei, agg);
    gemm_epi_kernel<true ><<<gemmGrid, 256>>>(agg, W1a, b1a, g1a, be1a, m1a, v1a, tmp, N_NODES);
    gemm_epi_kernel<false><<<gemmGrid, 256>>>(tmp, W2a, b2a, nullptr, nullptr, nullptr, nullptr, h1, N_NODES);

    // layer 2
    copy_kernel<<<copyGrid, 256>>>(h1, agg);
    scatter_kernel<<<scatGrid, 256>>>(h1, ei, agg);
    gemm_epi_kernel<true ><<<gemmGrid, 256>>>(agg, W1b, b1b, g1b, be1b, m1b, v1b, tmp, N_NODES);
    gemm_epi_kernel<false><<<gemmGrid, 256>>>(tmp, W2b, b2b, nullptr, nullptr, nullptr, nullptr, h2, N_NODES);

    // pooling
    zero_pool_kernel<<<(N_GRAPHS * 2 * DIM + 255) / 256, 256>>>();
    pool_kernel<<<((N_NODES + 15) / 16 + 7) / 8, 256>>>(h1, h2, batch);

    // head
    head_kernel<<<(N_GRAPHS + 7) / 8, 256>>>(lin1W, lin1b, lin2W, lin2b, out);
}

// round 2
// speedup vs baseline: 1.8092x; 1.8092x over previous
#include <cuda_runtime.h>

#define N_NODES 50000
#define N_EDGES 800000
#define DIM 256
#define N_GRAPHS 500
#define N_OUT 10
#define BN_EPS 1e-5f

// ---------------- scratch (static device globals; no allocation) ----------------
__device__ float g_agg[(size_t)N_NODES * DIM];
__device__ float g_tmp[(size_t)N_NODES * DIM];
__device__ float g_h1[(size_t)N_NODES * DIM];
__device__ float g_h2[(size_t)N_NODES * DIM];
__device__ float g_pool[(size_t)N_GRAPHS * 2 * DIM];
__device__ int   g_idx_is64;
__device__ int   g_counts[N_NODES];
__device__ int   g_rowptr[N_NODES + 1];
__device__ int   g_cursor[N_NODES];
__device__ int   g_esrc[N_EDGES];

// ---------------- dtype detection (int64 vs int32 indices) ----------------
__global__ void detect_kernel(const long long* __restrict__ ei) {
    if (threadIdx.x == 0 && blockIdx.x == 0) {
        int ok = 1;
        for (int i = 0; i < 64; i++) {
            long long v = ei[i];
            if (v < 0 || v >= N_NODES) ok = 0;
        }
        g_idx_is64 = ok;
    }
}

__device__ __forceinline__ int load_idx(const void* p, int i) {
    if (g_idx_is64) return (int)((const long long*)p)[i];
    return ((const int*)p)[i];
}

// ---------------- CSR build ----------------
__global__ void zero_counts_kernel() {
    int i = blockIdx.x * blockDim.x + threadIdx.x;
    if (i < N_NODES) g_counts[i] = 0;
}

__global__ void hist_kernel(const void* __restrict__ ei) {
    int e = blockIdx.x * blockDim.x + threadIdx.x;
    if (e >= N_EDGES) return;
    int d = load_idx(ei, N_EDGES + e);
    atomicAdd(&g_counts[d], 1);
}

// single-block exclusive scan over g_counts -> g_rowptr, g_cursor
__global__ void scan_kernel() {
    __shared__ int sdata[1024];
    __shared__ int carry;
    int tid = threadIdx.x;
    if (tid == 0) carry = 0;
    __syncthreads();
    for (int base = 0; base < N_NODES; base += 1024) {
        int i = base + tid;
        int v = (i < N_NODES) ? g_counts[i] : 0;
        sdata[tid] = v;
        __syncthreads();
        for (int off = 1; off < 1024; off <<= 1) {
            int t = (tid >= off) ? sdata[tid - off] : 0;
            __syncthreads();
            sdata[tid] += t;
            __syncthreads();
        }
        int incl = sdata[tid];
        int excl = incl - v;
        if (i < N_NODES) {
            int r = carry + excl;
            g_rowptr[i] = r;
            g_cursor[i] = r;
        }
        __syncthreads();
        if (tid == 1023) carry += incl;
        __syncthreads();
    }
    if (tid == 0) g_rowptr[N_NODES] = carry;
}

__global__ void fill_kernel(const void* __restrict__ ei) {
    int e = blockIdx.x * blockDim.x + threadIdx.x;
    if (e >= N_EDGES) return;
    int s = load_idx(ei, e);
    int d = load_idx(ei, N_EDGES + e);
    int pos = atomicAdd(&g_cursor[d], 1);
    g_esrc[pos] = s;
}

// ---------------- gather aggregation: agg[i] = x[i] + sum_{e->i} x[src] ----------------
__global__ __launch_bounds__(256) void agg_kernel(const float* __restrict__ x,
                                                  float* __restrict__ agg) {
    int node = blockIdx.x * 8 + (threadIdx.x >> 5);
    if (node >= N_NODES) return;
    int lane = threadIdx.x & 31;
    const float4* xv = (const float4*)x;
    float4 acc0 = xv[(size_t)node * 64 + lane];
    float4 acc1 = xv[(size_t)node * 64 + 32 + lane];
    int start = g_rowptr[node];
    int end   = g_rowptr[node + 1];
    for (int k = start; k < end; k++) {
        int s = g_esrc[k];
        const float4* xs = xv + (size_t)s * 64;
        float4 v0 = xs[lane];
        float4 v1 = xs[lane + 32];
        acc0.x += v0.x; acc0.y += v0.y; acc0.z += v0.z; acc0.w += v0.w;
        acc1.x += v1.x; acc1.y += v1.y; acc1.z += v1.z; acc1.w += v1.w;
    }
    float4* av = (float4*)agg;
    av[(size_t)node * 64 + lane] = acc0;
    av[(size_t)node * 64 + 32 + lane] = acc1;
}

// ---------------- fused GEMM (M x 256 @ 256 x 256) + bias [+BN] + ReLU ----------------
// BM=128, BN=128, BK=16, TM=TN=8, 256 threads, double-buffered smem.
template <bool DO_BN>
__global__ __launch_bounds__(256) void gemm_epi_kernel(
    const float* __restrict__ A, const float* __restrict__ W,
    const float* __restrict__ bias,
    const float* __restrict__ gamma, const float* __restrict__ beta,
    const float* __restrict__ mean,  const float* __restrict__ var,
    float* __restrict__ C, int M)
{
    __shared__ float As[2][16][128];
    __shared__ float Bs[2][16][128];
    const int tid = threadIdx.x;
    const int ty = tid >> 4;          // 0..15
    const int tx = tid & 15;          // 0..15
    const int rowBase = blockIdx.x * 128;
    const int colBase = blockIdx.y * 128;

    const int aRow  = tid >> 2;       // 0..63
    const int aCol  = (tid & 3) * 4;  // 0,4,8,12
    const int bRow  = tid >> 5;       // 0..7
    const int bCol  = (tid & 31) * 4; // 0..124

    float acc[8][8];
#pragma unroll
    for (int i = 0; i < 8; i++)
#pragma unroll
        for (int j = 0; j < 8; j++) acc[i][j] = 0.f;

    // prefetch registers
    float4 pa0, pa1, pb0, pb1;
    {
        int r0 = rowBase + aRow;       int rc0 = r0 < M ? r0 : (M - 1);
        int r1 = rowBase + aRow + 64;  int rc1 = r1 < M ? r1 : (M - 1);
        pa0 = *(const float4*)(A + (size_t)rc0 * 256 + aCol);
        pa1 = *(const float4*)(A + (size_t)rc1 * 256 + aCol);
        pb0 = *(const float4*)(W + (size_t)(bRow)     * 256 + colBase + bCol);
        pb1 = *(const float4*)(W + (size_t)(bRow + 8) * 256 + colBase + bCol);
    }

    int p = 0;
    for (int kt = 0; kt < 256; kt += 16) {
        // store prefetched tile into smem buffer p
        As[p][aCol + 0][aRow]      = pa0.x;
        As[p][aCol + 1][aRow]      = pa0.y;
        As[p][aCol + 2][aRow]      = pa0.z;
        As[p][aCol + 3][aRow]      = pa0.w;
        As[p][aCol + 0][aRow + 64] = pa1.x;
        As[p][aCol + 1][aRow + 64] = pa1.y;
        As[p][aCol + 2][aRow + 64] = pa1.z;
        As[p][aCol + 3][aRow + 64] = pa1.w;
        *(float4*)&Bs[p][bRow][bCol]     = pb0;
        *(float4*)&Bs[p][bRow + 8][bCol] = pb1;
        __syncthreads();

        if (kt + 16 < 256) {
            int k2 = kt + 16;
            int r0 = rowBase + aRow;       int rc0 = r0 < M ? r0 : (M - 1);
            int r1 = rowBase + aRow + 64;  int rc1 = r1 < M ? r1 : (M - 1);
            pa0 = *(const float4*)(A + (size_t)rc0 * 256 + k2 + aCol);
            pa1 = *(const float4*)(A + (size_t)rc1 * 256 + k2 + aCol);
            pb0 = *(const float4*)(W + (size_t)(k2 + bRow)     * 256 + colBase + bCol);
            pb1 = *(const float4*)(W + (size_t)(k2 + bRow + 8) * 256 + colBase + bCol);
        }

#pragma unroll
        for (int k = 0; k < 16; k++) {
            float a[8], b[8];
            *(float4*)(a)     = *(const float4*)&As[p][k][ty * 8];
            *(float4*)(a + 4) = *(const float4*)&As[p][k][ty * 8 + 4];
            *(float4*)(b)     = *(const float4*)&Bs[p][k][tx * 8];
            *(float4*)(b + 4) = *(const float4*)&Bs[p][k][tx * 8 + 4];
#pragma unroll
            for (int i = 0; i < 8; i++)
#pragma unroll
                for (int j = 0; j < 8; j++)
                    acc[i][j] = fmaf(a[i], b[j], acc[i][j]);
        }
        p ^= 1;
    }

    // epilogue: out = relu(acc*sc + sh)
    float sc[8], sh[8];
#pragma unroll
    for (int j = 0; j < 8; j++) {
        int c = colBase + tx * 8 + j;
        float bv = bias[c];
        if (DO_BN) {
            float s = gamma[c] * rsqrtf(var[c] + BN_EPS);
            sc[j] = s;
            sh[j] = beta[c] - mean[c] * s + bv * s;
        } else {
            sc[j] = 1.f;
            sh[j] = bv;
        }
    }
#pragma unroll
    for (int i = 0; i < 8; i++) {
        int r = rowBase + ty * 8 + i;
        if (r < M) {
            float4 o0, o1;
            o0.x = fmaxf(acc[i][0] * sc[0] + sh[0], 0.f);
            o0.y = fmaxf(acc[i][1] * sc[1] + sh[1], 0.f);
            o0.z = fmaxf(acc[i][2] * sc[2] + sh[2], 0.f);
            o0.w = fmaxf(acc[i][3] * sc[3] + sh[3], 0.f);
            o1.x = fmaxf(acc[i][4] * sc[4] + sh[4], 0.f);
            o1.y = fmaxf(acc[i][5] * sc[5] + sh[5], 0.f);
            o1.z = fmaxf(acc[i][6] * sc[6] + sh[6], 0.f);
            o1.w = fmaxf(acc[i][7] * sc[7] + sh[7], 0.f);
            float* crow = C + (size_t)r * 256 + colBase + tx * 8;
            *(float4*)(crow)     = o0;
            *(float4*)(crow + 4) = o1;
        }
    }
}

// ---------------- pooling ----------------
__global__ void zero_pool_kernel() {
    int i = blockIdx.x * blockDim.x + threadIdx.x;
    if (i < N_GRAPHS * 2 * DIM) g_pool[i] = 0.f;
}

__global__ void pool_kernel(const float* __restrict__ h1, const float* __restrict__ h2,
                            const void* __restrict__ batch) {
    int wid = blockIdx.x * 8 + (threadIdx.x >> 5);
    int base = wid * 16;
    if (base >= N_NODES) return;
    int lane = threadIdx.x & 31;
    int end = base + 16; if (end > N_NODES) end = N_NODES;

    float4 a0 = {0,0,0,0}, a1 = {0,0,0,0}, b0 = {0,0,0,0}, b1 = {0,0,0,0};
    int cur = load_idx(batch, base);
    for (int n = base; n < end; n++) {
        int g = load_idx(batch, n);
        if (g != cur) {
            float* p = g_pool + (size_t)cur * 512 + lane * 4;
            atomicAdd(p + 0, a0.x); atomicAdd(p + 1, a0.y); atomicAdd(p + 2, a0.z); atomicAdd(p + 3, a0.w);
            atomicAdd(p + 128, a1.x); atomicAdd(p + 129, a1.y); atomicAdd(p + 130, a1.z); atomicAdd(p + 131, a1.w);
            atomicAdd(p + 256, b0.x); atomicAdd(p + 257, b0.y); atomicAdd(p + 258, b0.z); atomicAdd(p + 259, b0.w);
            atomicAdd(p + 384, b1.x); atomicAdd(p + 385, b1.y); atomicAdd(p + 386, b1.z); atomicAdd(p + 387, b1.w);
            a0 = a1 = b0 = b1 = make_float4(0,0,0,0);
            cur = g;
        }
        const float4* r1 = (const float4*)(h1 + (size_t)n * 256);
        const float4* r2 = (const float4*)(h2 + (size_t)n * 256);
        float4 v;
        v = r1[lane];      a0.x += v.x; a0.y += v.y; a0.z += v.z; a0.w += v.w;
        v = r1[lane + 32]; a1.x += v.x; a1.y += v.y; a1.z += v.z; a1.w += v.w;
        v = r2[lane];      b0.x += v.x; b0.y += v.y; b0.z += v.z; b0.w += v.w;
        v = r2[lane + 32]; b1.x += v.x; b1.y += v.y; b1.z += v.z; b1.w += v.w;
    }
    float* p = g_pool + (size_t)cur * 512 + lane * 4;
    atomicAdd(p + 0, a0.x); atomicAdd(p + 1, a0.y); atomicAdd(p + 2, a0.z); atomicAdd(p + 3, a0.w);
    atomicAdd(p + 128, a1.x); atomicAdd(p + 129, a1.y); atomicAdd(p + 130, a1.z); atomicAdd(p + 131, a1.w);
    atomicAdd(p + 256, b0.x); atomicAdd(p + 257, b0.y); atomicAdd(p + 258, b0.z); atomicAdd(p + 259, b0.w);
    atomicAdd(p + 384, b1.x); atomicAdd(p + 385, b1.y); atomicAdd(p + 386, b1.z); atomicAdd(p + 387, b1.w);
}

// ---------------- head ----------------
__global__ __launch_bounds__(256) void head_kernel(
    const float* __restrict__ W1, const float* __restrict__ b1,
    const float* __restrict__ W2, const float* __restrict__ b2,
    float* __restrict__ out)
{
    __shared__ float Ps[8][512];
    __shared__ float Hs[8][768];
    __shared__ float Os[8][10];
    int tid = threadIdx.x;
    int rowBase = blockIdx.x * 8;
    int nrows = N_GRAPHS - rowBase; if (nrows > 8) nrows = 8;

    for (int i = tid; i < 8 * 512; i += 256) {
        int r = i >> 9, c = i & 511;
        Ps[r][c] = (r < nrows) ? g_pool[(size_t)(rowBase + r) * 512 + c] : 0.f;
    }
    __syncthreads();

    for (int n = tid; n < 768; n += 256) {
        float acc[8];
#pragma unroll
        for (int r = 0; r < 8; r++) acc[r] = 0.f;
        for (int k = 0; k < 512; k++) {
            float w = W1[(size_t)k * 768 + n];
#pragma unroll
            for (int r = 0; r < 8; r++) acc[r] = fmaf(Ps[r][k], w, acc[r]);
        }
        float bb = b1[n];
#pragma unroll
        for (int r = 0; r < 8; r++) Hs[r][n] = fmaxf(acc[r] + bb, 0.f);
    }
    __syncthreads();

    if (tid < 80) {
        int r = tid / 10, c = tid % 10;
        float acc = b2[c];
        for (int k = 0; k < 768; k++) acc = fmaf(Hs[r][k], W2[(size_t)k * 10 + c], acc);
        Os[r][c] = acc;
    }
    __syncthreads();

    if (tid < nrows) {
        int r = tid;
        float mx = -1e30f;
        for (int c = 0; c < 10; c++) mx = fmaxf(mx, Os[r][c]);
        float s = 0.f;
        for (int c = 0; c < 10; c++) s += expf(Os[r][c] - mx);
        float lse = mx + logf(s);
        for (int c = 0; c < 10; c++) out[(size_t)(rowBase + r) * 10 + c] = Os[r][c] - lse;
    }
}

// ---------------- launch ----------------
extern "C" void kernel_launch(void* const* d_in, const int* in_sizes, int n_in,
                              void* d_out, int out_size) {
    const float* x     = (const float*)d_in[0];
    const void*  ei    = d_in[1];
    const void*  batch = d_in[2];
    const float* W1a = (const float*)d_in[3];
    const float* b1a = (const float*)d_in[4];
    const float* g1a = (const float*)d_in[5];
    const float* be1a= (const float*)d_in[6];
    const float* m1a = (const float*)d_in[7];
    const float* v1a = (const float*)d_in[8];
    const float* W2a = (const float*)d_in[9];
    const float* b2a = (const float*)d_in[10];
    const float* W1b = (const float*)d_in[11];
    const float* b1b = (const float*)d_in[12];
    const float* g1b = (const float*)d_in[13];
    const float* be1b= (const float*)d_in[14];
    const float* m1b = (const float*)d_in[15];
    const float* v1b = (const float*)d_in[16];
    const float* W2b = (const float*)d_in[17];
    const float* b2b = (const float*)d_in[18];
    const float* lin1W = (const float*)d_in[19];
    const float* lin1b = (const float*)d_in[20];
    const float* lin2W = (const float*)d_in[21];
    const float* lin2b = (const float*)d_in[22];
    float* out = (float*)d_out;

    float *agg, *tmp, *h1, *h2;
    cudaGetSymbolAddress((void**)&agg, g_agg);
    cudaGetSymbolAddress((void**)&tmp, g_tmp);
    cudaGetSymbolAddress((void**)&h1,  g_h1);
    cudaGetSymbolAddress((void**)&h2,  g_h2);

    dim3 gemmGrid((N_NODES + 127) / 128, 2);
    const int aggGrid = (N_NODES + 7) / 8;

    detect_kernel<<<1, 32>>>((const long long*)ei);

    // CSR build (shared by both layers)
    zero_counts_kernel<<<(N_NODES + 255) / 256, 256>>>();
    hist_kernel<<<(N_EDGES + 255) / 256, 256>>>(ei);
    scan_kernel<<<1, 1024>>>();
    fill_kernel<<<(N_EDGES + 255) / 256, 256>>>(ei);

    // layer 1
    agg_kernel<<<aggGrid, 256>>>(x, agg);
    gemm_epi_kernel<true ><<<gemmGrid, 256>>>(agg, W1a, b1a, g1a, be1a, m1a, v1a, tmp, N_NODES);
    gemm_epi_kernel<false><<<gemmGrid, 256>>>(tmp, W2a, b2a, nullptr, nullptr, nullptr, nullptr, h1, N_NODES);

    // layer 2
    agg_kernel<<<aggGrid, 256>>>(h1, agg);
    gemm_epi_kernel<true ><<<gemmGrid, 256>>>(agg, W1b, b1b, g1b, be1b, m1b, v1b, tmp, N_NODES);
    gemm_epi_kernel<false><<<gemmGrid, 256>>>(tmp, W2b, b2b, nullptr, nullptr, nullptr, nullptr, h2, N_NODES);

    // pooling
    zero_pool_kernel<<<(N_GRAPHS * 2 * DIM + 255) / 256, 256>>>();
    pool_kernel<<<((N_NODES + 15) / 16 + 7) / 8, 256>>>(h1, h2, batch);

    // head
    head_kernel<<<(N_GRAPHS + 7) / 8, 256>>>(lin1W, lin1b, lin2W, lin2b, out);
}

// round 4
// speedup vs baseline: 3.1329x; 1.7317x over previous
#include <cuda_runtime.h>
#include <cuda_bf16.h>
#include <cstdint>

#define N_NODES 50000
#define N_EDGES 800000
#define DIM 256
#define N_GRAPHS 500
#define N_OUT 10
#define BN_EPS 1e-5f

// ---------------- scratch ----------------
__device__ float g_agg[(size_t)N_NODES * DIM];
__device__ float g_tmp[(size_t)N_NODES * DIM];
__device__ float g_h1[(size_t)N_NODES * DIM];
__device__ float g_h2[(size_t)N_NODES * DIM];
__device__ float g_pool[(size_t)N_GRAPHS * 2 * DIM];
__device__ int   g_idx_is64;
__device__ int   g_counts[N_NODES];
__device__ int   g_rowptr[N_NODES + 1];
__device__ int   g_cursor[N_NODES];
__device__ int   g_esrc[N_EDGES];
__device__ int   g_partials[64];
__device__ int   g_poff[64];
// split+transposed weights, swizzled: [slot][part][kchunk][nhalf][r=128][64]
__device__ __nv_bfloat16 g_wt[4 * 2 * 4 * 2 * 128 * 64];

// ---------------- dtype detection ----------------
__global__ void detect_kernel(const long long* __restrict__ ei) {
    if (threadIdx.x == 0 && blockIdx.x == 0) {
        int ok = 1;
        for (int i = 0; i < 64; i++) {
            long long v = ei[i];
            if (v < 0 || v >= N_NODES) ok = 0;
        }
        g_idx_is64 = ok;
    }
}
__device__ __forceinline__ int load_idx(const void* p, int i) {
    if (g_idx_is64) return (int)((const long long*)p)[i];
    return ((const int*)p)[i];
}

// ---------------- CSR build ----------------
__global__ void zero_counts_kernel() {
    int i = blockIdx.x * blockDim.x + threadIdx.x;
    if (i < N_NODES) g_counts[i] = 0;
}
__global__ void hist_kernel(const void* __restrict__ ei) {
    int e = blockIdx.x * blockDim.x + threadIdx.x;
    if (e >= N_EDGES) return;
    atomicAdd(&g_counts[load_idx(ei, N_EDGES + e)], 1);
}
__global__ void scan1_kernel() {
    __shared__ int wsum[32];
    int tid = threadIdx.x;
    int i = blockIdx.x * 1024 + tid;
    int v = (i < N_NODES) ? g_counts[i] : 0;
    int s = v;
    int lane = tid & 31;
#pragma unroll
    for (int o = 1; o < 32; o <<= 1) {
        int t = __shfl_up_sync(0xffffffffu, s, o);
        if (lane >= o) s += t;
    }
    if (lane == 31) wsum[tid >> 5] = s;
    __syncthreads();
    if (tid < 32) {
        int ws = wsum[tid];
#pragma unroll
        for (int o = 1; o < 32; o <<= 1) {
            int t = __shfl_up_sync(0xffffffffu, ws, o);
            if (tid >= o) ws += t;
        }
        wsum[tid] = ws;
    }
    __syncthreads();
    int off = (tid >= 32) ? wsum[(tid >> 5) - 1] : 0;
    int incl = s + off;
    if (i < N_NODES) g_rowptr[i] = incl - v;
    if (tid == 1023) g_partials[blockIdx.x] = incl;
}
__global__ void scan2_kernel(int nblk) {
    if (threadIdx.x == 0 && blockIdx.x == 0) {
        int acc = 0;
        for (int b = 0; b < nblk; b++) { g_poff[b] = acc; acc += g_partials[b]; }
    }
}
__global__ void scan3_kernel() {
    int i = blockIdx.x * 1024 + threadIdx.x;
    if (i < N_NODES) {
        int r = g_rowptr[i] + g_poff[blockIdx.x];
        g_rowptr[i] = r;
        g_cursor[i] = r;
    }
    if (i == 0) g_rowptr[N_NODES] = N_EDGES;
}
__global__ void fill_kernel(const void* __restrict__ ei) {
    int e = blockIdx.x * blockDim.x + threadIdx.x;
    if (e >= N_EDGES) return;
    int s = load_idx(ei, e);
    int d = load_idx(ei, N_EDGES + e);
    g_esrc[atomicAdd(&g_cursor[d], 1)] = s;
}

// ---------------- gather aggregation ----------------
__global__ __launch_bounds__(256) void agg_kernel(const float* __restrict__ x,
                                                  float* __restrict__ agg) {
    int node = blockIdx.x * 8 + (threadIdx.x >> 5);
    if (node >= N_NODES) return;
    int lane = threadIdx.x & 31;
    const float4* xv = (const float4*)x;
    float4 acc0 = xv[(size_t)node * 64 + lane];
    float4 acc1 = xv[(size_t)node * 64 + 32 + lane];
    int start = g_rowptr[node];
    int end   = g_rowptr[node + 1];
    for (int k = start; k < end; k++) {
        int s = g_esrc[k];
        const float4* xs = xv + (size_t)s * 64;
        float4 v0 = xs[lane];
        float4 v1 = xs[lane + 32];
        acc0.x += v0.x; acc0.y += v0.y; acc0.z += v0.z; acc0.w += v0.w;
        acc1.x += v1.x; acc1.y += v1.y; acc1.z += v1.z; acc1.w += v1.w;
    }
    float4* av = (float4*)agg;
    av[(size_t)node * 64 + lane] = acc0;
    av[(size_t)node * 64 + 32 + lane] = acc1;
}

// ---------------- weight transpose + bf16 split, swizzled ----------------
// W is [k=256][n=256]. Dest tile for (kchunk c, nhalf h): rows r = n&127 (128),
// cols kl = k&63 (64 bf16 = 8 chunks of 8), chunk position swizzled cc^(r&7).
__global__ void wconv_kernel(const float* __restrict__ W, int slot) {
    int id = blockIdx.x * blockDim.x + threadIdx.x;   // 65536
    int k = id >> 8, n = id & 255;
    float v = W[(size_t)k * 256 + n];
    __nv_bfloat16 hi = __float2bfloat16(v);
    __nv_bfloat16 lo = __float2bfloat16(v - __bfloat162float(hi));
    int c = k >> 6, kl = k & 63, h = n >> 7, r = n & 127;
    int cc = kl >> 3, ci = kl & 7;
    size_t pos = ((size_t)(cc ^ (r & 7)) << 3) + ci + ((size_t)r << 6);
    size_t tile0 = ((((size_t)(slot * 2 + 0) * 4 + c) * 2 + h) << 13);
    size_t tile1 = ((((size_t)(slot * 2 + 1) * 4 + c) * 2 + h) << 13);
    g_wt[tile0 + pos] = hi;
    g_wt[tile1 + pos] = lo;
}

// ---------------- mma.sync helpers ----------------
__device__ __forceinline__ uint32_t smem_u32(const void* p) {
    uint32_t a;
    asm("{ .reg .u64 t; cvta.to.shared.u64 t, %1; cvt.u32.u64 %0, t; }" : "=r"(a) : "l"(p));
    return a;
}
__device__ __forceinline__ void ldx4(uint32_t* r, uint32_t addr) {
    asm volatile("ldmatrix.sync.aligned.m8n8.x4.shared.b16 {%0,%1,%2,%3}, [%4];"
                 : "=r"(r[0]), "=r"(r[1]), "=r"(r[2]), "=r"(r[3]) : "r"(addr));
}
__device__ __forceinline__ void ldx2(uint32_t* r, uint32_t addr) {
    asm volatile("ldmatrix.sync.aligned.m8n8.x2.shared.b16 {%0,%1}, [%2];"
                 : "=r"(r[0]), "=r"(r[1]) : "r"(addr));
}
__device__ __forceinline__ void mma16816(float* d, const uint32_t* a, const uint32_t* b) {
    asm volatile("mma.sync.aligned.m16n8k16.row.col.f32.bf16.bf16.f32 "
                 "{%0,%1,%2,%3}, {%4,%5,%6,%7}, {%8,%9}, {%0,%1,%2,%3};"
                 : "+f"(d[0]), "+f"(d[1]), "+f"(d[2]), "+f"(d[3])
                 : "r"(a[0]), "r"(a[1]), "r"(a[2]), "r"(a[3]), "r"(b[0]), "r"(b[1]));
}

// ---------------- split-bf16 tensor-core GEMM via mma.sync ----------------
// C[M,256] = relu(epi(A @ W)); grid (ceil(M/128), 2), 256 threads.
// smem: Ah, Al, Bh, Bl each 128x64 bf16 (16KB), XOR-swizzled 16B chunks.
#define GSM_BYTES (65536 + 1024)

template <bool DO_BN>
__global__ __launch_bounds__(256, 2) void gemm_mma_kernel(
    const float* __restrict__ A, int wslot,
    const float* __restrict__ bias,
    const float* __restrict__ gamma, const float* __restrict__ beta,
    const float* __restrict__ mean,  const float* __restrict__ var,
    float* __restrict__ C, int M)
{
    extern __shared__ char dsm[];
    uint32_t sb0 = smem_u32(dsm);
    uint32_t sb = (sb0 + 1023u) & ~1023u;
    char* ub = dsm + (sb - sb0);

    const int tid = threadIdx.x, wid = tid >> 5, lane = tid & 31;
    const int rowBase = blockIdx.x * 128;
    const int wm = (wid >> 2) * 64;       // warp row base within tile
    const int wn = (wid & 3) * 32;        // warp col base within tile

    const uint32_t sA_hi = sb, sA_lo = sb + 16384, sB_hi = sb + 32768, sB_lo = sb + 49152;

    // lane-derived ldmatrix address components
    const int lr = lane & 7;
    const int ag = lane >> 3;                 // 0..3
    const int aRowOff = (ag & 1) * 8 + lr;    // row within 16-row frag
    const int aCc = ag >> 1;                  // 0/1: k halves
    const int bCc = (lane >> 3) & 1;          // 0/1
    uint32_t aRowByte[4], bRowByte[4];
#pragma unroll
    for (int mi = 0; mi < 4; mi++) aRowByte[mi] = (uint32_t)(wm + mi * 16 + aRowOff) << 7;
#pragma unroll
    for (int ni = 0; ni < 4; ni++) bRowByte[ni] = (uint32_t)(wn + ni * 8 + lr) << 7;

    float acc[4][4][4];
#pragma unroll
    for (int mi = 0; mi < 4; mi++)
#pragma unroll
        for (int ni = 0; ni < 4; ni++)
#pragma unroll
            for (int q = 0; q < 4; q++) acc[mi][ni][q] = 0.f;

    const float4* A4 = (const float4*)A;

    for (int c = 0; c < 4; c++) {
        // ---- fill A hi/lo (convert fp32 -> split bf16, swizzled) ----
#pragma unroll
        for (int i = 0; i < 4; i++) {
            int id = tid + i * 256;          // 0..1023
            int r = id >> 3, cc = id & 7;
            int gr = rowBase + r; if (gr >= M) gr = M - 1;
            const float4* src = A4 + (size_t)gr * 64 + c * 16 + cc * 2;
            float4 v0 = src[0], v1 = src[1];
            __nv_bfloat162 h0 = __floats2bfloat162_rn(v0.x, v0.y);
            __nv_bfloat162 h1 = __floats2bfloat162_rn(v0.z, v0.w);
            __nv_bfloat162 h2 = __floats2bfloat162_rn(v1.x, v1.y);
            __nv_bfloat162 h3 = __floats2bfloat162_rn(v1.z, v1.w);
            __nv_bfloat162 l0 = __floats2bfloat162_rn(v0.x - __bfloat162float(h0.x), v0.y - __bfloat162float(h0.y));
            __nv_bfloat162 l1 = __floats2bfloat162_rn(v0.z - __bfloat162float(h1.x), v0.w - __bfloat162float(h1.y));
            __nv_bfloat162 l2 = __floats2bfloat162_rn(v1.x - __bfloat162float(h2.x), v1.y - __bfloat162float(h2.y));
            __nv_bfloat162 l3 = __floats2bfloat162_rn(v1.z - __bfloat162float(h3.x), v1.w - __bfloat162float(h3.y));
            uint32_t off = ((uint32_t)r << 7) + ((uint32_t)(cc ^ (r & 7)) << 4);
            uint4 hv = make_uint4(*(uint32_t*)&h0, *(uint32_t*)&h1, *(uint32_t*)&h2, *(uint32_t*)&h3);
            uint4 lv = make_uint4(*(uint32_t*)&l0, *(uint32_t*)&l1, *(uint32_t*)&l2, *(uint32_t*)&l3);
            *(uint4*)(ub + off) = hv;                 // Ah at offset 0
            *(uint4*)(ub + 16384 + off) = lv;         // Al
        }
        // ---- fill B hi/lo (linear copy of pre-swizzled tiles) ----
        {
            const uint4* bh = (const uint4*)(g_wt + ((((size_t)(wslot * 2 + 0) * 4 + c) * 2 + blockIdx.y) << 13));
            const uint4* bl = (const uint4*)(g_wt + ((((size_t)(wslot * 2 + 1) * 4 + c) * 2 + blockIdx.y) << 13));
            uint4* sh = (uint4*)(ub + 32768);
            uint4* sl = (uint4*)(ub + 49152);
#pragma unroll
            for (int i = 0; i < 4; i++) {
                sh[tid + i * 256] = bh[tid + i * 256];
                sl[tid + i * 256] = bl[tid + i * 256];
            }
        }
        __syncthreads();

        // ---- compute: 4 k16 steps, 3 product passes ----
#pragma unroll
        for (int ks = 0; ks < 4; ks++) {
            uint32_t ah[4][4];
#pragma unroll
            for (int mi = 0; mi < 4; mi++)
                ldx4(ah[mi], sA_hi + aRowByte[mi] + ((uint32_t)(((ks << 1) + aCc) ^ lr) << 4));
            uint32_t b[4][2];
#pragma unroll
            for (int ni = 0; ni < 4; ni++)
                ldx2(b[ni], sB_hi + bRowByte[ni] + ((uint32_t)(((ks << 1) + bCc) ^ lr) << 4));
            // Ah * Bh
#pragma unroll
            for (int mi = 0; mi < 4; mi++)
#pragma unroll
                for (int ni = 0; ni < 4; ni++) mma16816(acc[mi][ni], ah[mi], b[ni]);
            // Al * Bh (stream Al one frag at a time)
#pragma unroll
            for (int mi = 0; mi < 4; mi++) {
                uint32_t at[4];
                ldx4(at, sA_lo + aRowByte[mi] + ((uint32_t)(((ks << 1) + aCc) ^ lr) << 4));
#pragma unroll
                for (int ni = 0; ni < 4; ni++) mma16816(acc[mi][ni], at, b[ni]);
            }
            // Ah * Bl
#pragma unroll
            for (int ni = 0; ni < 4; ni++)
                ldx2(b[ni], sB_lo + bRowByte[ni] + ((uint32_t)(((ks << 1) + bCc) ^ lr) << 4));
#pragma unroll
            for (int mi = 0; mi < 4; mi++)
#pragma unroll
                for (int ni = 0; ni < 4; ni++) mma16816(acc[mi][ni], ah[mi], b[ni]);
        }
        __syncthreads();
    }

    // ---- epilogue ----
    float sc[4][2], sh[4][2];
#pragma unroll
    for (int ni = 0; ni < 4; ni++) {
#pragma unroll
        for (int j = 0; j < 2; j++) {
            int col = blockIdx.y * 128 + wn + ni * 8 + (lane & 3) * 2 + j;
            float bv = bias[col];
            if (DO_BN) {
                float s = gamma[col] * rsqrtf(var[col] + BN_EPS);
                sc[ni][j] = s;
                sh[ni][j] = beta[col] - mean[col] * s + bv * s;
            } else {
                sc[ni][j] = 1.f;
                sh[ni][j] = bv;
            }
        }
    }
#pragma unroll
    for (int mi = 0; mi < 4; mi++) {
        int r0 = rowBase + wm + mi * 16 + (lane >> 2);
        int r1 = r0 + 8;
#pragma unroll
        for (int ni = 0; ni < 4; ni++) {
            int col0 = blockIdx.y * 128 + wn + ni * 8 + (lane & 3) * 2;
            if (r0 < M) {
                float2 o;
                o.x = fmaxf(acc[mi][ni][0] * sc[ni][0] + sh[ni][0], 0.f);
                o.y = fmaxf(acc[mi][ni][1] * sc[ni][1] + sh[ni][1], 0.f);
                *(float2*)(C + (size_t)r0 * 256 + col0) = o;
            }
            if (r1 < M) {
                float2 o;
                o.x = fmaxf(acc[mi][ni][2] * sc[ni][0] + sh[ni][0], 0.f);
                o.y = fmaxf(acc[mi][ni][3] * sc[ni][1] + sh[ni][1], 0.f);
                *(float2*)(C + (size_t)r1 * 256 + col0) = o;
            }
        }
    }
}

// ---------------- pooling ----------------
__global__ void zero_pool_kernel() {
    int i = blockIdx.x * blockDim.x + threadIdx.x;
    if (i < N_GRAPHS * 2 * DIM) g_pool[i] = 0.f;
}
__global__ void pool_kernel(const float* __restrict__ h1, const float* __restrict__ h2,
                            const void* __restrict__ batch) {
    int wid = blockIdx.x * 8 + (threadIdx.x >> 5);
    int base = wid * 16;
    if (base >= N_NODES) return;
    int lane = threadIdx.x & 31;
    int end = base + 16; if (end > N_NODES) end = N_NODES;

    float4 a0 = {0,0,0,0}, a1 = {0,0,0,0}, b0 = {0,0,0,0}, b1 = {0,0,0,0};
    int cur = load_idx(batch, base);
    for (int n = base; n < end; n++) {
        int g = load_idx(batch, n);
        if (g != cur) {
            float* p = g_pool + (size_t)cur * 512 + lane * 4;
            atomicAdd(p + 0, a0.x); atomicAdd(p + 1, a0.y); atomicAdd(p + 2, a0.z); atomicAdd(p + 3, a0.w);
            atomicAdd(p + 128, a1.x); atomicAdd(p + 129, a1.y); atomicAdd(p + 130, a1.z); atomicAdd(p + 131, a1.w);
            atomicAdd(p + 256, b0.x); atomicAdd(p + 257, b0.y); atomicAdd(p + 258, b0.z); atomicAdd(p + 259, b0.w);
            atomicAdd(p + 384, b1.x); atomicAdd(p + 385, b1.y); atomicAdd(p + 386, b1.z); atomicAdd(p + 387, b1.w);
            a0 = a1 = b0 = b1 = make_float4(0,0,0,0);
            cur = g;
        }
        const float4* r1 = (const float4*)(h1 + (size_t)n * 256);
        const float4* r2 = (const float4*)(h2 + (size_t)n * 256);
        float4 v;
        v = r1[lane];      a0.x += v.x; a0.y += v.y; a0.z += v.z; a0.w += v.w;
        v = r1[lane + 32]; a1.x += v.x; a1.y += v.y; a1.z += v.z; a1.w += v.w;
        v = r2[lane];      b0.x += v.x; b0.y += v.y; b0.z += v.z; b0.w += v.w;
        v = r2[lane + 32]; b1.x += v.x; b1.y += v.y; b1.z += v.z; b1.w += v.w;
    }
    float* p = g_pool + (size_t)cur * 512 + lane * 4;
    atomicAdd(p + 0, a0.x); atomicAdd(p + 1, a0.y); atomicAdd(p + 2, a0.z); atomicAdd(p + 3, a0.w);
    atomicAdd(p + 128, a1.x); atomicAdd(p + 129, a1.y); atomicAdd(p + 130, a1.z); atomicAdd(p + 131, a1.w);
    atomicAdd(p + 256, b0.x); atomicAdd(p + 257, b0.y); atomicAdd(p + 258, b0.z); atomicAdd(p + 259, b0.w);
    atomicAdd(p + 384, b1.x); atomicAdd(p + 385, b1.y); atomicAdd(p + 386, b1.z); atomicAdd(p + 387, b1.w);
}

// ---------------- head ----------------
__global__ __launch_bounds__(256) void head_kernel(
    const float* __restrict__ W1, const float* __restrict__ b1,
    const float* __restrict__ W2, const float* __restrict__ b2,
    float* __restrict__ out)
{
    __shared__ float Ps[8][512];
    __shared__ float Hs[8][768];
    __shared__ float Os[8][10];
    int tid = threadIdx.x;
    int rowBase = blockIdx.x * 8;
    int nrows = N_GRAPHS - rowBase; if (nrows > 8) nrows = 8;

    for (int i = tid; i < 8 * 512; i += 256) {
        int r = i >> 9, c = i & 511;
        Ps[r][c] = (r < nrows) ? g_pool[(size_t)(rowBase + r) * 512 + c] : 0.f;
    }
    __syncthreads();

    for (int n = tid; n < 768; n += 256) {
        float acc[8];
#pragma unroll
        for (int r = 0; r < 8; r++) acc[r] = 0.f;
        for (int k = 0; k < 512; k++) {
            float w = W1[(size_t)k * 768 + n];
#pragma unroll
            for (int r = 0; r < 8; r++) acc[r] = fmaf(Ps[r][k], w, acc[r]);
        }
        float bb = b1[n];
#pragma unroll
        for (int r = 0; r < 8; r++) Hs[r][n] = fmaxf(acc[r] + bb, 0.f);
    }
    __syncthreads();

    if (tid < 80) {
        int r = tid / 10, c = tid % 10;
        float acc = b2[c];
        for (int k = 0; k < 768; k++) acc = fmaf(Hs[r][k], W2[(size_t)k * 10 + c], acc);
        Os[r][c] = acc;
    }
    __syncthreads();

    if (tid < nrows) {
        int r = tid;
        float mx = -1e30f;
        for (int c = 0; c < 10; c++) mx = fmaxf(mx, Os[r][c]);
        float s = 0.f;
        for (int c = 0; c < 10; c++) s += expf(Os[r][c] - mx);
        float lse = mx + logf(s);
        for (int c = 0; c < 10; c++) out[(size_t)(rowBase + r) * 10 + c] = Os[r][c] - lse;
    }
}

// ---------------- launch ----------------
extern "C" void kernel_launch(void* const* d_in, const int* in_sizes, int n_in,
                              void* d_out, int out_size) {
    const float* x     = (const float*)d_in[0];
    const void*  ei    = d_in[1];
    const void*  batch = d_in[2];
    const float* W1a = (const float*)d_in[3];
    const float* b1a = (const float*)d_in[4];
    const float* g1a = (const float*)d_in[5];
    const float* be1a= (const float*)d_in[6];
    const float* m1a = (const float*)d_in[7];
    const float* v1a = (const float*)d_in[8];
    const float* W2a = (const float*)d_in[9];
    const float* b2a = (const float*)d_in[10];
    const float* W1b = (const float*)d_in[11];
    const float* b1b = (const float*)d_in[12];
    const float* g1b = (const float*)d_in[13];
    const float* be1b= (const float*)d_in[14];
    const float* m1b = (const float*)d_in[15];
    const float* v1b = (const float*)d_in[16];
    const float* W2b = (const float*)d_in[17];
    const float* b2b = (const float*)d_in[18];
    const float* lin1W = (const float*)d_in[19];
    const float* lin1b = (const float*)d_in[20];
    const float* lin2W = (const float*)d_in[21];
    const float* lin2b = (const float*)d_in[22];
    float* out = (float*)d_out;

    float *agg, *tmp, *h1, *h2;
    cudaGetSymbolAddress((void**)&agg, g_agg);
    cudaGetSymbolAddress((void**)&tmp, g_tmp);
    cudaGetSymbolAddress((void**)&h1,  g_h1);
    cudaGetSymbolAddress((void**)&h2,  g_h2);

    cudaFuncSetAttribute(gemm_mma_kernel<true>,  cudaFuncAttributeMaxDynamicSharedMemorySize, GSM_BYTES);
    cudaFuncSetAttribute(gemm_mma_kernel<false>, cudaFuncAttributeMaxDynamicSharedMemorySize, GSM_BYTES);

    dim3 gemmGrid((N_NODES + 127) / 128, 2);
    const int aggGrid  = (N_NODES + 7) / 8;
    const int scanGrid = (N_NODES + 1023) / 1024; // 49

    detect_kernel<<<1, 32>>>((const long long*)ei);

    // weight prep
    wconv_kernel<<<256, 256>>>(W1a, 0);
    wconv_kernel<<<256, 256>>>(W2a, 1);
    wconv_kernel<<<256, 256>>>(W1b, 2);
    wconv_kernel<<<256, 256>>>(W2b, 3);

    // CSR build
    zero_counts_kernel<<<(N_NODES + 255) / 256, 256>>>();
    hist_kernel<<<(N_EDGES + 255) / 256, 256>>>(ei);
    scan1_kernel<<<scanGrid, 1024>>>();
    scan2_kernel<<<1, 32>>>(scanGrid);
    scan3_kernel<<<scanGrid, 1024>>>();
    fill_kernel<<<(N_EDGES + 255) / 256, 256>>>(ei);

    // layer 1
    agg_kernel<<<aggGrid, 256>>>(x, agg);
    gemm_mma_kernel<true ><<<gemmGrid, 256, GSM_BYTES>>>(agg, 0, b1a, g1a, be1a, m1a, v1a, tmp, N_NODES);
    gemm_mma_kernel<false><<<gemmGrid, 256, GSM_BYTES>>>(tmp, 1, b2a, nullptr, nullptr, nullptr, nullptr, h1, N_NODES);

    // layer 2
    agg_kernel<<<aggGrid, 256>>>(h1, agg);
    gemm_mma_kernel<true ><<<gemmGrid, 256, GSM_BYTES>>>(agg, 2, b1b, g1b, be1b, m1b, v1b, tmp, N_NODES);
    gemm_mma_kernel<false><<<gemmGrid, 256, GSM_BYTES>>>(tmp, 3, b2b, nullptr, nullptr, nullptr, nullptr, h2, N_NODES);

    // pooling
    zero_pool_kernel<<<(N_GRAPHS * 2 * DIM + 255) / 256, 256>>>();
    pool_kernel<<<((N_NODES + 15) / 16 + 7) / 8, 256>>>(h1, h2, batch);

    // head
    head_kernel<<<(N_GRAPHS + 7) / 8, 256>>>(lin1W, lin1b, lin2W, lin2b, out);
}

// round 5
// speedup vs baseline: 3.3891x; 1.0818x over previous
#include <cuda_runtime.h>
#include <cuda_bf16.h>
#include <cstdint>

#define N_NODES 50000
#define N_EDGES 800000
#define DIM 256
#define N_GRAPHS 500
#define N_OUT 10
#define BN_EPS 1e-5f

#define N_TILES 391              // ceil(50000/128)
#define TILE_BYTES 131072        // 8 chunks * 2 parts * 8192

// ---------------- scratch ----------------
__device__ unsigned char g_pl0[(size_t)N_TILES * TILE_BYTES];  // split-bf16 planes ping
__device__ unsigned char g_pl1[(size_t)N_TILES * TILE_BYTES];  // split-bf16 planes pong
__device__ float g_h1[(size_t)N_NODES * DIM];
__device__ float g_h2[(size_t)N_NODES * DIM];
__device__ float g_pool[(size_t)N_GRAPHS * 2 * DIM];
__device__ int   g_idx_is64;
__device__ int   g_counts[N_NODES];
__device__ int   g_rowptr[N_NODES + 1];
__device__ int   g_cursor[N_NODES];
__device__ int   g_esrc[N_EDGES];
__device__ int   g_partials[64];
__device__ int   g_poff[64];
// weights: [slot][chunk=8][nhalf=2][part=2][8192B]
__device__ unsigned char g_wt[4 * 262144];

// ---------------- helpers ----------------
__device__ __forceinline__ uint32_t smem_u32(const void* p) {
    uint32_t a;
    asm("{ .reg .u64 t; cvta.to.shared.u64 t, %1; cvt.u32.u64 %0, t; }" : "=r"(a) : "l"(p));
    return a;
}
__device__ __forceinline__ void cp16(uint32_t s, const void* g) {
    asm volatile("cp.async.cg.shared.global [%0], [%1], 16;"
                 :: "r"(s), "l"(__cvta_generic_to_global(g)) : "memory");
}
__device__ __forceinline__ void cp_commit() { asm volatile("cp.async.commit_group;" ::: "memory"); }
__device__ __forceinline__ void ldx4(uint32_t* r, uint32_t addr) {
    asm volatile("ldmatrix.sync.aligned.m8n8.x4.shared.b16 {%0,%1,%2,%3}, [%4];"
                 : "=r"(r[0]), "=r"(r[1]), "=r"(r[2]), "=r"(r[3]) : "r"(addr));
}
__device__ __forceinline__ void ldx2(uint32_t* r, uint32_t addr) {
    asm volatile("ldmatrix.sync.aligned.m8n8.x2.shared.b16 {%0,%1}, [%2];"
                 : "=r"(r[0]), "=r"(r[1]) : "r"(addr));
}
__device__ __forceinline__ void mma16816(float* d, const uint32_t* a, const uint32_t* b) {
    asm volatile("mma.sync.aligned.m16n8k16.row.col.f32.bf16.bf16.f32 "
                 "{%0,%1,%2,%3}, {%4,%5,%6,%7}, {%8,%9}, {%0,%1,%2,%3};"
                 : "+f"(d[0]), "+f"(d[1]), "+f"(d[2]), "+f"(d[3])
                 : "r"(a[0]), "r"(a[1]), "r"(a[2]), "r"(a[3]), "r"(b[0]), "r"(b[1]));
}
// swizzled byte offset of 16B chunk (row r in 0..127, ccol in 0..3) within an 8KB tile
__device__ __forceinline__ uint32_t tswz(int r, int ccol) {
    int rr = r >> 1;
    return ((uint32_t)rr << 7) + ((uint32_t)((ccol + ((r & 1) << 2)) ^ (rr & 7)) << 4);
}
__device__ __forceinline__ uint32_t packbf2(float a, float b) {
    __nv_bfloat162 h = __floats2bfloat162_rn(a, b);
    return *(uint32_t*)&h;
}

// ---------------- dtype detection ----------------
__global__ void detect_kernel(const long long* __restrict__ ei) {
    if (threadIdx.x == 0 && blockIdx.x == 0) {
        int ok = 1;
        for (int i = 0; i < 64; i++) {
            long long v = ei[i];
            if (v < 0 || v >= N_NODES) ok = 0;
        }
        g_idx_is64 = ok;
    }
}
__device__ __forceinline__ int load_idx(const void* p, int i) {
    if (g_idx_is64) return (int)((const long long*)p)[i];
    return ((const int*)p)[i];
}

// ---------------- CSR build ----------------
__global__ void zero_counts_kernel() {
    int i = blockIdx.x * blockDim.x + threadIdx.x;
    if (i < N_NODES) g_counts[i] = 0;
}
__global__ void hist_kernel(const void* __restrict__ ei) {
    int e = blockIdx.x * blockDim.x + threadIdx.x;
    if (e >= N_EDGES) return;
    atomicAdd(&g_counts[load_idx(ei, N_EDGES + e)], 1);
}
__global__ void scan1_kernel() {
    __shared__ int wsum[32];
    int tid = threadIdx.x;
    int i = blockIdx.x * 1024 + tid;
    int v = (i < N_NODES) ? g_counts[i] : 0;
    int s = v;
    int lane = tid & 31;
#pragma unroll
    for (int o = 1; o < 32; o <<= 1) {
        int t = __shfl_up_sync(0xffffffffu, s, o);
        if (lane >= o) s += t;
    }
    if (lane == 31) wsum[tid >> 5] = s;
    __syncthreads();
    if (tid < 32) {
        int ws = wsum[tid];
#pragma unroll
        for (int o = 1; o < 32; o <<= 1) {
            int t = __shfl_up_sync(0xffffffffu, ws, o);
            if (tid >= o) ws += t;
        }
        wsum[tid] = ws;
    }
    __syncthreads();
    int off = (tid >= 32) ? wsum[(tid >> 5) - 1] : 0;
    int incl = s + off;
    if (i < N_NODES) g_rowptr[i] = incl - v;
    if (tid == 1023) g_partials[blockIdx.x] = incl;
}
__global__ void scan2_kernel(int nblk) {
    if (threadIdx.x == 0 && blockIdx.x == 0) {
        int acc = 0;
        for (int b = 0; b < nblk; b++) { g_poff[b] = acc; acc += g_partials[b]; }
    }
}
__global__ void scan3_kernel() {
    int i = blockIdx.x * 1024 + threadIdx.x;
    if (i < N_NODES) {
        int r = g_rowptr[i] + g_poff[blockIdx.x];
        g_rowptr[i] = r;
        g_cursor[i] = r;
    }
    if (i == 0) g_rowptr[N_NODES] = N_EDGES;
}
__global__ void fill_kernel(const void* __restrict__ ei) {
    int e = blockIdx.x * blockDim.x + threadIdx.x;
    if (e >= N_EDGES) return;
    int s = load_idx(ei, e);
    int d = load_idx(ei, N_EDGES + e);
    g_esrc[atomicAdd(&g_cursor[d], 1)] = s;
}

// ---------------- gather aggregation -> split-bf16 swizzled planes ----------------
__global__ __launch_bounds__(256) void agg_kernel(const float* __restrict__ x,
                                                  unsigned char* __restrict__ Op) {
    int node = blockIdx.x * 8 + (threadIdx.x >> 5);
    if (node >= N_NODES) return;
    int lane = threadIdx.x & 31;
    const float4* xv = (const float4*)x;
    float4 acc0 = xv[(size_t)node * 64 + lane];
    float4 acc1 = xv[(size_t)node * 64 + 32 + lane];
    int start = g_rowptr[node];
    int end   = g_rowptr[node + 1];
    for (int k = start; k < end; k++) {
        int s = g_esrc[k];
        const float4* xs = xv + (size_t)s * 64;
        float4 v0 = xs[lane];
        float4 v1 = xs[lane + 32];
        acc0.x += v0.x; acc0.y += v0.y; acc0.z += v0.z; acc0.w += v0.w;
        acc1.x += v1.x; acc1.y += v1.y; acc1.z += v1.z; acc1.w += v1.w;
    }
    // write split-bf16 planes: cols lane*4..+3 (chunk c0) and 128+lane*4..+3 (chunk c0+4)
    int tile = node >> 7, r = node & 127;
    int ccol = (lane >> 1) & 3;
    int c0 = lane >> 3;
    uint32_t off = tswz(r, ccol) + (uint32_t)(lane & 1) * 8;
    unsigned char* base = Op + (size_t)tile * TILE_BYTES;
    uint32_t h0 = packbf2(acc0.x, acc0.y), h1 = packbf2(acc0.z, acc0.w);
    float hx, hy;
    hx = __bfloat162float(__float2bfloat16(acc0.x)); hy = __bfloat162float(__float2bfloat16(acc0.y));
    uint32_t l0 = packbf2(acc0.x - hx, acc0.y - hy);
    hx = __bfloat162float(__float2bfloat16(acc0.z)); hy = __bfloat162float(__float2bfloat16(acc0.w));
    uint32_t l1 = packbf2(acc0.z - hx, acc0.w - hy);
    *(uint2*)(base + (size_t)c0 * 16384 + off)        = make_uint2(h0, h1);
    *(uint2*)(base + (size_t)c0 * 16384 + 8192 + off) = make_uint2(l0, l1);
    uint32_t h2 = packbf2(acc1.x, acc1.y), h3 = packbf2(acc1.z, acc1.w);
    hx = __bfloat162float(__float2bfloat16(acc1.x)); hy = __bfloat162float(__float2bfloat16(acc1.y));
    uint32_t l2 = packbf2(acc1.x - hx, acc1.y - hy);
    hx = __bfloat162float(__float2bfloat16(acc1.z)); hy = __bfloat162float(__float2bfloat16(acc1.w));
    uint32_t l3 = packbf2(acc1.z - hx, acc1.w - hy);
    *(uint2*)(base + (size_t)(c0 + 4) * 16384 + off)        = make_uint2(h2, h3);
    *(uint2*)(base + (size_t)(c0 + 4) * 16384 + 8192 + off) = make_uint2(l2, l3);
}

// ---------------- weight transpose + split into plane layout ----------------
__global__ void wconv_kernel(const float* __restrict__ W, int slot) {
    int id = blockIdx.x * blockDim.x + threadIdx.x;   // 65536
    int k = id >> 8, n = id & 255;
    float v = W[(size_t)k * 256 + n];
    __nv_bfloat16 hi = __float2bfloat16(v);
    __nv_bfloat16 lo = __float2bfloat16(v - __bfloat162float(hi));
    int c = k >> 5, kl = k & 31, h = n >> 7, r = n & 127;
    uint32_t off = tswz(r, kl >> 3) + (uint32_t)(kl & 7) * 2;
    size_t base = (size_t)slot * 262144 + (size_t)c * 32768 + (size_t)h * 16384;
    *(__nv_bfloat16*)(g_wt + base + off)        = hi;
    *(__nv_bfloat16*)(g_wt + base + 8192 + off) = lo;
}

// ---------------- pipelined split-bf16 tensor-core GEMM ----------------
// grid (N_TILES, 2), 256 threads. Per chunk: A hi/lo 16KB + B hi/lo 16KB, double buffered.
#define GSM_BYTES (65536 + 1024)

template <bool DO_BN, bool OUT_PLANES>
__global__ __launch_bounds__(256, 2) void gemm_mma_kernel(
    const unsigned char* __restrict__ Ap, const unsigned char* __restrict__ Wslot,
    const float* __restrict__ bias,
    const float* __restrict__ gamma, const float* __restrict__ beta,
    const float* __restrict__ mean,  const float* __restrict__ var,
    float* __restrict__ C, unsigned char* __restrict__ Oplanes, int M)
{
    extern __shared__ char dsm[];
    uint32_t sb0 = smem_u32(dsm);
    uint32_t sb = (sb0 + 1023u) & ~1023u;

    const int tid = threadIdx.x, wid = tid >> 5, lane = tid & 31;
    const int rowBase = blockIdx.x * 128;
    const int nh = blockIdx.y;
    const int wm = (wid >> 2) * 64;
    const int wn = (wid & 3) * 32;

    const int lr = lane & 7;
    const int ag = lane >> 3;
    const int aRowOff = (ag & 1) * 8 + lr;
    const int aCc = ag >> 1;
    const int bCc = (lane >> 3) & 1;

    uint32_t aBase[4], bBase[4];
    int aXor[4], aS4[4], bXor[4], bS4[4];
#pragma unroll
    for (int mi = 0; mi < 4; mi++) {
        int r = wm + mi * 16 + aRowOff;
        aBase[mi] = (uint32_t)(r >> 1) << 7;
        aXor[mi] = (r >> 1) & 7;
        aS4[mi] = (r & 1) << 2;
    }
#pragma unroll
    for (int ni = 0; ni < 4; ni++) {
        int r = wn + ni * 8 + lr;
        bBase[ni] = (uint32_t)(r >> 1) << 7;
        bXor[ni] = (r >> 1) & 7;
        bS4[ni] = (r & 1) << 2;
    }

    float acc[4][4][4];
#pragma unroll
    for (int mi = 0; mi < 4; mi++)
#pragma unroll
        for (int ni = 0; ni < 4; ni++)
#pragma unroll
            for (int q = 0; q < 4; q++) acc[mi][ni][q] = 0.f;

    const unsigned char* Asrc = Ap + (size_t)blockIdx.x * TILE_BYTES;
    const unsigned char* Bsrc0 = Wslot + (size_t)nh * 16384;

    // prefetch chunk 0 into buffer 0
    {
        const unsigned char* ga = Asrc;
        const unsigned char* gb = Bsrc0;
#pragma unroll
        for (int j = 0; j < 4; j++) {
            int idx = tid + j * 256;
            cp16(sb + idx * 16, ga + idx * 16);
            cp16(sb + 16384 + idx * 16, gb + idx * 16);
        }
        cp_commit();
    }

    for (int c = 0; c < 8; c++) {
        int p = c & 1;
        if (c < 7) {
            uint32_t sB = sb + (p ^ 1) * 32768;
            const unsigned char* ga = Asrc + (size_t)(c + 1) * 16384;
            const unsigned char* gb = Bsrc0 + (size_t)(c + 1) * 32768;
#pragma unroll
            for (int j = 0; j < 4; j++) {
                int idx = tid + j * 256;
                cp16(sB + idx * 16, ga + idx * 16);
                cp16(sB + 16384 + idx * 16, gb + idx * 16);
            }
            cp_commit();
            asm volatile("cp.async.wait_group 1;" ::: "memory");
        } else {
            asm volatile("cp.async.wait_group 0;" ::: "memory");
        }
        __syncthreads();

        uint32_t sA_hi = sb + p * 32768;
        uint32_t sA_lo = sA_hi + 8192;
        uint32_t sB_hi = sA_hi + 16384;
        uint32_t sB_lo = sA_hi + 24576;

#pragma unroll
        for (int ks = 0; ks < 2; ks++) {
            int ka = ks * 2 + aCc;
            int kb = ks * 2 + bCc;
            uint32_t ah[4][4];
#pragma unroll
            for (int mi = 0; mi < 4; mi++)
                ldx4(ah[mi], sA_hi + aBase[mi] + ((uint32_t)((ka + aS4[mi]) ^ aXor[mi]) << 4));
            uint32_t b[4][2];
#pragma unroll
            for (int ni = 0; ni < 4; ni++)
                ldx2(b[ni], sB_hi + bBase[ni] + ((uint32_t)((kb + bS4[ni]) ^ bXor[ni]) << 4));
#pragma unroll
            for (int mi = 0; mi < 4; mi++)
#pragma unroll
                for (int ni = 0; ni < 4; ni++) mma16816(acc[mi][ni], ah[mi], b[ni]);
#pragma unroll
            for (int mi = 0; mi < 4; mi++) {
                uint32_t at[4];
                ldx4(at, sA_lo + aBase[mi] + ((uint32_t)((ka + aS4[mi]) ^ aXor[mi]) << 4));
#pragma unroll
                for (int ni = 0; ni < 4; ni++) mma16816(acc[mi][ni], at, b[ni]);
            }
#pragma unroll
            for (int ni = 0; ni < 4; ni++)
                ldx2(b[ni], sB_lo + bBase[ni] + ((uint32_t)((kb + bS4[ni]) ^ bXor[ni]) << 4));
#pragma unroll
            for (int mi = 0; mi < 4; mi++)
#pragma unroll
                for (int ni = 0; ni < 4; ni++) mma16816(acc[mi][ni], ah[mi], b[ni]);
        }
        __syncthreads();
    }

    // ---- epilogue ----
    float sc[4][2], sh[4][2];
#pragma unroll
    for (int ni = 0; ni < 4; ni++) {
#pragma unroll
        for (int j = 0; j < 2; j++) {
            int col = nh * 128 + wn + ni * 8 + (lane & 3) * 2 + j;
            float bv = bias[col];
            if (DO_BN) {
                float s = gamma[col] * rsqrtf(var[col] + BN_EPS);
                sc[ni][j] = s;
                sh[ni][j] = beta[col] - mean[col] * s + bv * s;
            } else {
                sc[ni][j] = 1.f;
                sh[ni][j] = bv;
            }
        }
    }
#pragma unroll
    for (int mi = 0; mi < 4; mi++) {
        int rl0 = wm + mi * 16 + (lane >> 2);
        int rl1 = rl0 + 8;
#pragma unroll
        for (int ni = 0; ni < 4; ni++) {
            int c0g = nh * 128 + wn + ni * 8 + (lane & 3) * 2;
            float v0 = fmaxf(acc[mi][ni][0] * sc[ni][0] + sh[ni][0], 0.f);
            float v1 = fmaxf(acc[mi][ni][1] * sc[ni][1] + sh[ni][1], 0.f);
            float v2 = fmaxf(acc[mi][ni][2] * sc[ni][0] + sh[ni][0], 0.f);
            float v3 = fmaxf(acc[mi][ni][3] * sc[ni][1] + sh[ni][1], 0.f);
            if (OUT_PLANES) {
                int ch = c0g >> 5, kl = c0g & 31;
                uint32_t bib = (uint32_t)(kl & 7) * 2;
                unsigned char* tb = Oplanes + (size_t)blockIdx.x * TILE_BYTES + (size_t)ch * 16384;
                if (rowBase + rl0 < M) {
                    uint32_t off = tswz(rl0, kl >> 3) + bib;
                    float h0 = __bfloat162float(__float2bfloat16(v0));
                    float h1 = __bfloat162float(__float2bfloat16(v1));
                    *(uint32_t*)(tb + off)        = packbf2(v0, v1);
                    *(uint32_t*)(tb + 8192 + off) = packbf2(v0 - h0, v1 - h1);
                }
                if (rowBase + rl1 < M) {
                    uint32_t off = tswz(rl1, kl >> 3) + bib;
                    float h2 = __bfloat162float(__float2bfloat16(v2));
                    float h3 = __bfloat162float(__float2bfloat16(v3));
                    *(uint32_t*)(tb + off)        = packbf2(v2, v3);
                    *(uint32_t*)(tb + 8192 + off) = packbf2(v2 - h2, v3 - h3);
                }
            } else {
                int r0 = rowBase + rl0, r1 = rowBase + rl1;
                if (r0 < M) { float2 o = {v0, v1}; *(float2*)(C + (size_t)r0 * 256 + c0g) = o; }
                if (r1 < M) { float2 o = {v2, v3}; *(float2*)(C + (size_t)r1 * 256 + c0g) = o; }
            }
        }
    }
}

// ---------------- pooling ----------------
__global__ void zero_pool_kernel() {
    int i = blockIdx.x * blockDim.x + threadIdx.x;
    if (i < N_GRAPHS * 2 * DIM) g_pool[i] = 0.f;
}
__global__ void pool_kernel(const float* __restrict__ h1, const float* __restrict__ h2,
                            const void* __restrict__ batch) {
    int wid = blockIdx.x * 8 + (threadIdx.x >> 5);
    int base = wid * 16;
    if (base >= N_NODES) return;
    int lane = threadIdx.x & 31;
    int end = base + 16; if (end > N_NODES) end = N_NODES;

    float4 a0 = {0,0,0,0}, a1 = {0,0,0,0}, b0 = {0,0,0,0}, b1 = {0,0,0,0};
    int cur = load_idx(batch, base);
    for (int n = base; n < end; n++) {
        int g = load_idx(batch, n);
        if (g != cur) {
            float* p = g_pool + (size_t)cur * 512 + lane * 4;
            atomicAdd(p + 0, a0.x); atomicAdd(p + 1, a0.y); atomicAdd(p + 2, a0.z); atomicAdd(p + 3, a0.w);
            atomicAdd(p + 128, a1.x); atomicAdd(p + 129, a1.y); atomicAdd(p + 130, a1.z); atomicAdd(p + 131, a1.w);
            atomicAdd(p + 256, b0.x); atomicAdd(p + 257, b0.y); atomicAdd(p + 258, b0.z); atomicAdd(p + 259, b0.w);
            atomicAdd(p + 384, b1.x); atomicAdd(p + 385, b1.y); atomicAdd(p + 386, b1.z); atomicAdd(p + 387, b1.w);
            a0 = a1 = b0 = b1 = make_float4(0,0,0,0);
            cur = g;
        }
        const float4* r1 = (const float4*)(h1 + (size_t)n * 256);
        const float4* r2 = (const float4*)(h2 + (size_t)n * 256);
        float4 v;
        v = r1[lane];      a0.x += v.x; a0.y += v.y; a0.z += v.z; a0.w += v.w;
        v = r1[lane + 32]; a1.x += v.x; a1.y += v.y; a1.z += v.z; a1.w += v.w;
        v = r2[lane];      b0.x += v.x; b0.y += v.y; b0.z += v.z; b0.w += v.w;
        v = r2[lane + 32]; b1.x += v.x; b1.y += v.y; b1.z += v.z; b1.w += v.w;
    }
    float* p = g_pool + (size_t)cur * 512 + lane * 4;
    atomicAdd(p + 0, a0.x); atomicAdd(p + 1, a0.y); atomicAdd(p + 2, a0.z); atomicAdd(p + 3, a0.w);
    atomicAdd(p + 128, a1.x); atomicAdd(p + 129, a1.y); atomicAdd(p + 130, a1.z); atomicAdd(p + 131, a1.w);
    atomicAdd(p + 256, b0.x); atomicAdd(p + 257, b0.y); atomicAdd(p + 258, b0.z); atomicAdd(p + 259, b0.w);
    atomicAdd(p + 384, b1.x); atomicAdd(p + 385, b1.y); atomicAdd(p + 386, b1.z); atomicAdd(p + 387, b1.w);
}

// ---------------- head ----------------
__global__ __launch_bounds__(256) void head_kernel(
    const float* __restrict__ W1, const float* __restrict__ b1,
    const float* __restrict__ W2, const float* __restrict__ b2,
    float* __restrict__ out)
{
    __shared__ float Ps[8][512];
    __shared__ float Hs[8][768];
    __shared__ float Os[8][10];
    int tid = threadIdx.x;
    int rowBase = blockIdx.x * 8;
    int nrows = N_GRAPHS - rowBase; if (nrows > 8) nrows = 8;

    for (int i = tid; i < 8 * 512; i += 256) {
        int r = i >> 9, c = i & 511;
        Ps[r][c] = (r < nrows) ? g_pool[(size_t)(rowBase + r) * 512 + c] : 0.f;
    }
    __syncthreads();

    for (int n = tid; n < 768; n += 256) {
        float acc[8];
#pragma unroll
        for (int r = 0; r < 8; r++) acc[r] = 0.f;
        for (int k = 0; k < 512; k++) {
            float w = W1[(size_t)k * 768 + n];
#pragma unroll
            for (int r = 0; r < 8; r++) acc[r] = fmaf(Ps[r][k], w, acc[r]);
        }
        float bb = b1[n];
#pragma unroll
        for (int r = 0; r < 8; r++) Hs[r][n] = fmaxf(acc[r] + bb, 0.f);
    }
    __syncthreads();

    if (tid < 80) {
        int r = tid / 10, c = tid % 10;
        float acc = b2[c];
        for (int k = 0; k < 768; k++) acc = fmaf(Hs[r][k], W2[(size_t)k * 10 + c], acc);
        Os[r][c] = acc;
    }
    __syncthreads();

    if (tid < nrows) {
        int r = tid;
        float mx = -1e30f;
        for (int c = 0; c < 10; c++) mx = fmaxf(mx, Os[r][c]);
        float s = 0.f;
        for (int c = 0; c < 10; c++) s += expf(Os[r][c] - mx);
        float lse = mx + logf(s);
        for (int c = 0; c < 10; c++) out[(size_t)(rowBase + r) * 10 + c] = Os[r][c] - lse;
    }
}

// ---------------- launch ----------------
extern "C" void kernel_launch(void* const* d_in, const int* in_sizes, int n_in,
                              void* d_out, int out_size) {
    const float* x     = (const float*)d_in[0];
    const void*  ei    = d_in[1];
    const void*  batch = d_in[2];
    const float* W1a = (const float*)d_in[3];
    const float* b1a = (const float*)d_in[4];
    const float* g1a = (const float*)d_in[5];
    const float* be1a= (const float*)d_in[6];
    const float* m1a = (const float*)d_in[7];
    const float* v1a = (const float*)d_in[8];
    const float* W2a = (const float*)d_in[9];
    const float* b2a = (const float*)d_in[10];
    const float* W1b = (const float*)d_in[11];
    const float* b1b = (const float*)d_in[12];
    const float* g1b = (const float*)d_in[13];
    const float* be1b= (const float*)d_in[14];
    const float* m1b = (const float*)d_in[15];
    const float* v1b = (const float*)d_in[16];
    const float* W2b = (const float*)d_in[17];
    const float* b2b = (const float*)d_in[18];
    const float* lin1W = (const float*)d_in[19];
    const float* lin1b = (const float*)d_in[20];
    const float* lin2W = (const float*)d_in[21];
    const float* lin2b = (const float*)d_in[22];
    float* out = (float*)d_out;

    unsigned char *pl0, *pl1, *wt;
    float *h1, *h2;
    cudaGetSymbolAddress((void**)&pl0, g_pl0);
    cudaGetSymbolAddress((void**)&pl1, g_pl1);
    cudaGetSymbolAddress((void**)&wt,  g_wt);
    cudaGetSymbolAddress((void**)&h1,  g_h1);
    cudaGetSymbolAddress((void**)&h2,  g_h2);

    cudaFuncSetAttribute(gemm_mma_kernel<true, true>,   cudaFuncAttributeMaxDynamicSharedMemorySize, GSM_BYTES);
    cudaFuncSetAttribute(gemm_mma_kernel<false, false>, cudaFuncAttributeMaxDynamicSharedMemorySize, GSM_BYTES);

    dim3 gemmGrid(N_TILES, 2);
    const int aggGrid  = (N_NODES + 7) / 8;
    const int scanGrid = (N_NODES + 1023) / 1024; // 49

    detect_kernel<<<1, 32>>>((const long long*)ei);

    // weight prep
    wconv_kernel<<<256, 256>>>(W1a, 0);
    wconv_kernel<<<256, 256>>>(W2a, 1);
    wconv_kernel<<<256, 256>>>(W1b, 2);
    wconv_kernel<<<256, 256>>>(W2b, 3);

    // CSR build
    zero_counts_kernel<<<(N_NODES + 255) / 256, 256>>>();
    hist_kernel<<<(N_EDGES + 255) / 256, 256>>>(ei);
    scan1_kernel<<<scanGrid, 1024>>>();
    scan2_kernel<<<1, 32>>>(scanGrid);
    scan3_kernel<<<scanGrid, 1024>>>();
    fill_kernel<<<(N_EDGES + 255) / 256, 256>>>(ei);

    // layer 1: agg(x)->pl0, gemm1(pl0)->pl1 (BN+ReLU, planes), gemm2(pl1)->h1 (fp32)
    agg_kernel<<<aggGrid, 256>>>(x, pl0);
    gemm_mma_kernel<true, true ><<<gemmGrid, 256, GSM_BYTES>>>(
        pl0, wt + 0 * 262144, b1a, g1a, be1a, m1a, v1a, nullptr, pl1, N_NODES);
    gemm_mma_kernel<false, false><<<gemmGrid, 256, GSM_BYTES>>>(
        pl1, wt + 1 * 262144, b2a, nullptr, nullptr, nullptr, nullptr, h1, nullptr, N_NODES);

    // layer 2
    agg_kernel<<<aggGrid, 256>>>(h1, pl0);
    gemm_mma_kernel<true, true ><<<gemmGrid, 256, GSM_BYTES>>>(
        pl0, wt + 2 * 262144, b1b, g1b, be1b, m1b, v1b, nullptr, pl1, N_NODES);
    gemm_mma_kernel<false, false><<<gemmGrid, 256, GSM_BYTES>>>(
        pl1, wt + 3 * 262144, b2b, nullptr, nullptr, nullptr, nullptr, h2, nullptr, N_NODES);

    // pooling
    zero_pool_kernel<<<(N_GRAPHS * 2 * DIM + 255) / 256, 256>>>();
    pool_kernel<<<((N_NODES + 15) / 16 + 7) / 8, 256>>>(h1, h2, batch);

    // head
    head_kernel<<<(N_GRAPHS + 7) / 8, 256>>>(lin1W, lin1b, lin2W, lin2b, out);
}